// round 1
// baseline (speedup 1.0000x reference)
#include <cuda_runtime.h>
#include <math.h>

#define BB 4
#define LL 512
#define ENCL 512
#define DD 1024
#define HH 16
#define HDD 64
#define MLPD 4096
#define RR 32

// ---------------- scratch (device globals; no allocations allowed) ----------
__device__ float g_xn [BB*LL*DD];
__device__ float g_q  [BB*LL*DD];
__device__ float g_k  [BB*LL*DD];
__device__ float g_v  [BB*LL*DD];
__device__ float g_sc [BB*HH*LL*LL];
__device__ float g_ctx[BB*LL*DD];
__device__ float g_x  [BB*LL*DD];
__device__ float g_y  [BB*LL*DD];
__device__ float g_low[BB*LL*RR];
__device__ float g_h0 [BB*LL*MLPD];
__device__ float g_h1 [BB*LL*MLPD];

// ---------------- rmsnorm ----------------
__global__ void rmsnorm_kernel(const float* __restrict__ X,
                               const float* __restrict__ sc,
                               float* __restrict__ O)
{
    long row = blockIdx.x;
    const float* x = X + row * DD;
    float* o = O + row * DD;
    int tid = threadIdx.x;
    float ss = 0.f;
    #pragma unroll
    for (int i = tid; i < DD; i += 256) { float v = x[i]; ss += v * v; }
    __shared__ float red[256];
    red[tid] = ss; __syncthreads();
    for (int st = 128; st > 0; st >>= 1) {
        if (tid < st) red[tid] += red[tid + st];
        __syncthreads();
    }
    float inv = rsqrtf(red[0] / (float)DD + 1e-6f);
    #pragma unroll
    for (int i = tid; i < DD; i += 256) o[i] = x[i] * inv * sc[i];
}

// ---------------- generic GEMM: C = alpha*(A@W + LA@LB) + Res ---------------
// A:[M,K] contiguous (per-batch stride sAb). W:[K,N] (stride sWb, 0 = shared).
// LA:[M,R] LB:[R,N] optional low-rank. Res optional.
__global__ void gemm_kernel(const float* __restrict__ A, long sAb,
                            const float* __restrict__ W, long sWb,
                            const float* __restrict__ LA, long sLAb,
                            const float* __restrict__ LB, long sLBb,
                            const float* __restrict__ Res, long sRb,
                            float* __restrict__ C, long sCb,
                            int M, int N, int K, float alpha)
{
    int b = blockIdx.z;
    A += (long)b * sAb;
    W += (long)b * sWb;
    if (LA) { LA += (long)b * sLAb; LB += (long)b * sLBb; }
    if (Res) Res += (long)b * sRb;
    C += (long)b * sCb;

    __shared__ float As[16][64];
    __shared__ float Bs[16][64];

    int tid = threadIdx.x;                // 256
    int tr = tid / 16, tc = tid % 16;     // 4x4 micro tile
    int rowBase = blockIdx.y * 64;
    int colBase = blockIdx.x * 64;

    int aRow = tid / 4;          // 0..63
    int aK   = (tid % 4) * 4;    // 0,4,8,12
    int bK   = tid / 16;         // 0..15
    int bCol = (tid % 16) * 4;   // 0..60

    float acc[4][4] = {};

    for (int k0 = 0; k0 < K; k0 += 16) {
        #pragma unroll
        for (int i = 0; i < 4; i++)
            As[aK + i][aRow] = A[(long)(rowBase + aRow) * K + (k0 + aK + i)];
        {
            int kk = k0 + bK;
            #pragma unroll
            for (int j = 0; j < 4; j++) {
                int c = colBase + bCol + j;
                Bs[bK][bCol + j] = (c < N) ? W[(long)kk * N + c] : 0.f;
            }
        }
        __syncthreads();
        #pragma unroll
        for (int kk = 0; kk < 16; kk++) {
            float a0[4], b0[4];
            #pragma unroll
            for (int i = 0; i < 4; i++) a0[i] = As[kk][tr * 4 + i];
            #pragma unroll
            for (int j = 0; j < 4; j++) b0[j] = Bs[kk][tc * 4 + j];
            #pragma unroll
            for (int i = 0; i < 4; i++)
                #pragma unroll
                for (int j = 0; j < 4; j++)
                    acc[i][j] += a0[i] * b0[j];
        }
        __syncthreads();
    }

    if (LA) {  // low-rank extra K = RR = 32
        for (int k0 = 0; k0 < RR; k0 += 16) {
            #pragma unroll
            for (int i = 0; i < 4; i++)
                As[aK + i][aRow] = LA[(long)(rowBase + aRow) * RR + (k0 + aK + i)];
            {
                int kk = k0 + bK;
                #pragma unroll
                for (int j = 0; j < 4; j++) {
                    int c = colBase + bCol + j;
                    Bs[bK][bCol + j] = (c < N) ? LB[(long)kk * N + c] : 0.f;
                }
            }
            __syncthreads();
            #pragma unroll
            for (int kk = 0; kk < 16; kk++) {
                float a0[4], b0[4];
                #pragma unroll
                for (int i = 0; i < 4; i++) a0[i] = As[kk][tr * 4 + i];
                #pragma unroll
                for (int j = 0; j < 4; j++) b0[j] = Bs[kk][tc * 4 + j];
                #pragma unroll
                for (int i = 0; i < 4; i++)
                    #pragma unroll
                    for (int j = 0; j < 4; j++)
                        acc[i][j] += a0[i] * b0[j];
            }
            __syncthreads();
        }
    }

    #pragma unroll
    for (int i = 0; i < 4; i++) {
        int r = rowBase + tr * 4 + i;
        #pragma unroll
        for (int j = 0; j < 4; j++) {
            int c = colBase + tc * 4 + j;
            if (c < N) {
                float v = acc[i][j] * alpha;
                if (Res) v += Res[(long)r * N + c];
                C[(long)r * N + c] = v;
            }
        }
    }
}

// ---------------- attention scores: S[b,h,q,k] = Q.Kt (+ T5 bias) ------------
__global__ void score_kernel(const float* __restrict__ Q,
                             const float* __restrict__ Km,
                             const float* __restrict__ rel_table, // null => no bias
                             float* __restrict__ S,
                             int Lq, int Lk)
{
    int z = blockIdx.z; int b = z / HH; int h = z % HH;
    const float* q = Q + (long)b * Lq * DD + h * HDD;
    const float* k = Km + (long)b * Lk * DD + h * HDD;
    float* s = S + (long)z * Lq * Lk;

    __shared__ float Qs[32][HDD];
    __shared__ float Ks[32][HDD];

    int tid = threadIdx.x;
    int qBase = blockIdx.y * 32, kBase = blockIdx.x * 32;
    for (int i = tid; i < 32 * HDD; i += 256) {
        int r = i / HDD, c = i % HDD;
        Qs[r][c] = q[(long)(qBase + r) * DD + c];
        Ks[r][c] = k[(long)(kBase + r) * DD + c];
    }
    __syncthreads();

    int tr = tid / 16, tc = tid % 16;   // 2x2 micro
    float acc[2][2] = {};
    #pragma unroll
    for (int d = 0; d < HDD; d++) {
        float a0 = Qs[tr * 2][d], a1 = Qs[tr * 2 + 1][d];
        float b0 = Ks[tc * 2][d], b1 = Ks[tc * 2 + 1][d];
        acc[0][0] += a0 * b0; acc[0][1] += a0 * b1;
        acc[1][0] += a1 * b0; acc[1][1] += a1 * b1;
    }
    #pragma unroll
    for (int i = 0; i < 2; i++)
        #pragma unroll
        for (int j = 0; j < 2; j++) {
            int qq = qBase + tr * 2 + i, kk = kBase + tc * 2 + j;
            float v = acc[i][j];
            if (rel_table) {
                int n = qq - kk; if (n < 0) n = 0;     // distance into the past
                int bucket;
                if (n < 16) bucket = n;
                else {
                    int lg = (int)(logf((float)n / 16.0f) / logf(8.0f) * 16.0f);
                    bucket = 16 + lg; if (bucket > 31) bucket = 31;
                }
                v += rel_table[bucket * HH + h];
                if (kk > qq) v += -1e10f;               // causal mask
            }
            s[(long)qq * Lk + kk] = v;
        }
}

// ---------------- softmax over last dim (row = Lk floats) -------------------
__global__ void softmax_kernel(float* __restrict__ S, int Lk)
{
    long row = blockIdx.x;
    float* s = S + row * Lk;
    int tid = threadIdx.x;
    __shared__ float red[256];

    float m = -INFINITY;
    for (int i = tid; i < Lk; i += 256) m = fmaxf(m, s[i]);
    red[tid] = m; __syncthreads();
    for (int st = 128; st > 0; st >>= 1) {
        if (tid < st) red[tid] = fmaxf(red[tid], red[tid + st]);
        __syncthreads();
    }
    m = red[0]; __syncthreads();

    float sum = 0.f;
    for (int i = tid; i < Lk; i += 256) {
        float e = expf(s[i] - m);
        s[i] = e; sum += e;
    }
    red[tid] = sum; __syncthreads();
    for (int st = 128; st > 0; st >>= 1) {
        if (tid < st) red[tid] += red[tid + st];
        __syncthreads();
    }
    float inv = 1.f / red[0];
    for (int i = tid; i < Lk; i += 256) s[i] *= inv;
}

// ---------------- ctx: O[b,q,h*HD+d] = sum_k P[b,h,q,k] * V[b,k,h*HD+d] -----
__global__ void ctx_kernel(const float* __restrict__ P,
                           const float* __restrict__ V,
                           float* __restrict__ O,
                           int Lq, int Lk)
{
    int z = blockIdx.z; int b = z / HH; int h = z % HH;
    const float* p = P + (long)z * Lq * Lk;
    const float* v = V + (long)b * Lk * DD + h * HDD;
    float* o = O + (long)b * Lq * DD + h * HDD;

    __shared__ float Ps[16][64];
    __shared__ float Vs[16][64];

    int tid = threadIdx.x;
    int rowBase = blockIdx.y * 64;
    int tr = tid / 16, tc = tid % 16;
    int aRow = tid / 4; int aK = (tid % 4) * 4;
    int bK = tid / 16; int bCol = (tid % 16) * 4;

    float acc[4][4] = {};
    for (int k0 = 0; k0 < Lk; k0 += 16) {
        #pragma unroll
        for (int i = 0; i < 4; i++)
            Ps[aK + i][aRow] = p[(long)(rowBase + aRow) * Lk + k0 + aK + i];
        #pragma unroll
        for (int j = 0; j < 4; j++)
            Vs[bK][bCol + j] = v[(long)(k0 + bK) * DD + bCol + j];
        __syncthreads();
        #pragma unroll
        for (int kk = 0; kk < 16; kk++) {
            float a0[4], b0[4];
            #pragma unroll
            for (int i = 0; i < 4; i++) a0[i] = Ps[kk][tr * 4 + i];
            #pragma unroll
            for (int j = 0; j < 4; j++) b0[j] = Vs[kk][tc * 4 + j];
            #pragma unroll
            for (int i = 0; i < 4; i++)
                #pragma unroll
                for (int j = 0; j < 4; j++)
                    acc[i][j] += a0[i] * b0[j];
        }
        __syncthreads();
    }
    #pragma unroll
    for (int i = 0; i < 4; i++)
        #pragma unroll
        for (int j = 0; j < 4; j++)
            o[(long)(rowBase + tr * 4 + i) * DD + tc * 4 + j] = acc[i][j];
}

// ---------------- gated gelu: h0 = gelu(h0) * h1 ----------------------------
__global__ void gelu_mul_kernel(float* __restrict__ h0,
                                const float* __restrict__ h1, long n)
{
    long i = (long)blockIdx.x * blockDim.x + threadIdx.x;
    if (i < n) {
        float x = h0[i];
        float g = 0.5f * x * (1.0f + erff(x * 0.70710678118654752f));
        h0[i] = g * h1[i];
    }
}

// ---------------- host side -------------------------------------------------
static float* sym_addr(const void* sym)
{
    void* p = nullptr;
    cudaGetSymbolAddress(&p, sym);
    return (float*)p;
}

static void launch_gemm(const float* A, long sA, const float* W, long sW,
                        const float* LA, long sLA, const float* LB, long sLB,
                        const float* Res, long sR, float* C, long sC,
                        int M, int N, int K, float alpha)
{
    dim3 g((N + 63) / 64, (M + 63) / 64, BB);
    gemm_kernel<<<g, 256>>>(A, sA, W, sW, LA, sLA, LB, sLB, Res, sR, C, sC, M, N, K, alpha);
}

extern "C" void kernel_launch(void* const* d_in, const int* in_sizes, int n_in,
                              void* d_out, int out_size)
{
    const float* inputs  = (const float*)d_in[0];
    const float* encoded = (const float*)d_in[1];
    const float* qa = (const float*)d_in[2];
    const float* qb = (const float*)d_in[3];
    const float* ka = (const float*)d_in[4];
    const float* kb = (const float*)d_in[5];
    const float* va = (const float*)d_in[6];
    const float* vb = (const float*)d_in[7];
    const float* oa = (const float*)d_in[8];
    const float* ob = (const float*)d_in[9];
    const float* rel = (const float*)d_in[10];
    const float* ln1 = (const float*)d_in[11];
    const float* ln2 = (const float*)d_in[12];
    const float* ln3 = (const float*)d_in[13];
    const float* sWq = (const float*)d_in[14];
    const float* sWk = (const float*)d_in[15];
    const float* sWv = (const float*)d_in[16];
    const float* sWo = (const float*)d_in[17];
    const float* cWq = (const float*)d_in[18];
    const float* cWk = (const float*)d_in[19];
    const float* cWv = (const float*)d_in[20];
    const float* cWo = (const float*)d_in[21];
    const float* wi0 = (const float*)d_in[22];
    const float* wi1 = (const float*)d_in[23];
    const float* wom = (const float*)d_in[24];
    float* out = (float*)d_out;

    float* xn  = sym_addr(g_xn);
    float* q   = sym_addr(g_q);
    float* k   = sym_addr(g_k);
    float* v   = sym_addr(g_v);
    float* sc  = sym_addr(g_sc);
    float* ctx = sym_addr(g_ctx);
    float* xres= sym_addr(g_x);
    float* yres= sym_addr(g_y);
    float* low = sym_addr(g_low);
    float* h0  = sym_addr(g_h0);
    float* h1  = sym_addr(g_h1);

    const long sBL = (long)LL * DD;          // per-batch stride of [B,L,D]
    const long sEN = (long)ENCL * DD;
    const long sLow = (long)LL * RR;
    const long sA2 = 2L * DD * RR;           // lora a: [B,2,D,R]
    const long sB2 = 2L * RR * DD;           // lora b: [B,2,R,D]
    const float qscale = 0.125f;             // 1/sqrt(64)

    // ===================== self-attention =====================
    rmsnorm_kernel<<<BB * LL, 256>>>(inputs, ln1, xn);

    // Q
    launch_gemm(xn, sBL, qa + 0, sA2, nullptr, 0, nullptr, 0, nullptr, 0,
                low, sLow, LL, RR, DD, 1.f);
    launch_gemm(xn, sBL, sWq, 0, low, sLow, qb + 0, sB2, nullptr, 0,
                q, sBL, LL, DD, DD, qscale);
    // K
    launch_gemm(xn, sBL, ka + 0, sA2, nullptr, 0, nullptr, 0, nullptr, 0,
                low, sLow, LL, RR, DD, 1.f);
    launch_gemm(xn, sBL, sWk, 0, low, sLow, kb + 0, sB2, nullptr, 0,
                k, sBL, LL, DD, DD, 1.f);
    // V
    launch_gemm(xn, sBL, va + 0, sA2, nullptr, 0, nullptr, 0, nullptr, 0,
                low, sLow, LL, RR, DD, 1.f);
    launch_gemm(xn, sBL, sWv, 0, low, sLow, vb + 0, sB2, nullptr, 0,
                v, sBL, LL, DD, DD, 1.f);

    {
        dim3 g(LL / 32, LL / 32, BB * HH);
        score_kernel<<<g, 256>>>(q, k, rel, sc, LL, LL);
    }
    softmax_kernel<<<BB * HH * LL, 256>>>(sc, LL);
    {
        dim3 g(1, LL / 64, BB * HH);
        ctx_kernel<<<g, 256>>>(sc, v, ctx, LL, LL);
    }
    // O (+ residual)
    launch_gemm(ctx, sBL, oa + 0, sA2, nullptr, 0, nullptr, 0, nullptr, 0,
                low, sLow, LL, RR, DD, 1.f);
    launch_gemm(ctx, sBL, sWo, 0, low, sLow, ob + 0, sB2, inputs, sBL,
                xres, sBL, LL, DD, DD, 1.f);

    // ===================== cross-attention =====================
    rmsnorm_kernel<<<BB * LL, 256>>>(xres, ln2, xn);

    // Q (from normed x)
    launch_gemm(xn, sBL, qa + DD * RR, sA2, nullptr, 0, nullptr, 0, nullptr, 0,
                low, sLow, LL, RR, DD, 1.f);
    launch_gemm(xn, sBL, cWq, 0, low, sLow, qb + RR * DD, sB2, nullptr, 0,
                q, sBL, LL, DD, DD, qscale);
    // K (from raw encoded)
    launch_gemm(encoded, sEN, ka + DD * RR, sA2, nullptr, 0, nullptr, 0, nullptr, 0,
                low, sLow, ENCL, RR, DD, 1.f);
    launch_gemm(encoded, sEN, cWk, 0, low, sLow, kb + RR * DD, sB2, nullptr, 0,
                k, sEN, ENCL, DD, DD, 1.f);
    // V
    launch_gemm(encoded, sEN, va + DD * RR, sA2, nullptr, 0, nullptr, 0, nullptr, 0,
                low, sLow, ENCL, RR, DD, 1.f);
    launch_gemm(encoded, sEN, cWv, 0, low, sLow, vb + RR * DD, sB2, nullptr, 0,
                v, sEN, ENCL, DD, DD, 1.f);

    {
        dim3 g(ENCL / 32, LL / 32, BB * HH);
        score_kernel<<<g, 256>>>(q, k, nullptr, sc, LL, ENCL);
    }
    softmax_kernel<<<BB * HH * LL, 256>>>(sc, ENCL);
    {
        dim3 g(1, LL / 64, BB * HH);
        ctx_kernel<<<g, 256>>>(sc, v, ctx, LL, ENCL);
    }
    launch_gemm(ctx, sBL, oa + DD * RR, sA2, nullptr, 0, nullptr, 0, nullptr, 0,
                low, sLow, LL, RR, DD, 1.f);
    launch_gemm(ctx, sBL, cWo, 0, low, sLow, ob + RR * DD, sB2, xres, sBL,
                yres, sBL, LL, DD, DD, 1.f);

    // ===================== MLP =====================
    rmsnorm_kernel<<<BB * LL, 256>>>(yres, ln3, xn);

    launch_gemm(xn, sBL, wi0, 0, nullptr, 0, nullptr, 0, nullptr, 0,
                h0, (long)LL * MLPD, LL, MLPD, DD, 1.f);
    launch_gemm(xn, sBL, wi1, 0, nullptr, 0, nullptr, 0, nullptr, 0,
                h1, (long)LL * MLPD, LL, MLPD, DD, 1.f);
    {
        long n = (long)BB * LL * MLPD;
        long nb = (n + 255) / 256;
        gelu_mul_kernel<<<(unsigned)nb, 256>>>(h0, h1, n);
    }
    launch_gemm(h0, (long)LL * MLPD, wom, 0, nullptr, 0, nullptr, 0, yres, sBL,
                out, sBL, LL, DD, MLPD, 1.f);

    (void)in_sizes; (void)n_in; (void)out_size;
}

// round 2
// speedup vs baseline: 1.0653x; 1.0653x over previous
#include <cuda_runtime.h>
#include <math.h>
#include <mma.h>

using namespace nvcuda;

#define BB 4
#define LL 512
#define ENCL 512
#define DD 1024
#define HH 16
#define HDD 64
#define MLPD 4096
#define RR 32

// ---------------- scratch (device globals) ----------------------------------
__device__ float g_xn [BB*LL*DD];
__device__ float g_q  [BB*LL*DD];
__device__ float g_k  [BB*LL*DD];
__device__ float g_v  [BB*LL*DD];
__device__ float g_sc [BB*HH*LL*LL];
__device__ float g_ctx[BB*LL*DD];
__device__ float g_x  [BB*LL*DD];
__device__ float g_y  [BB*LL*DD];
__device__ float g_low[BB*LL*RR];
__device__ float g_h0 [BB*LL*MLPD];
__device__ float g_h1 [BB*LL*MLPD];

// ---------------- tf32 split helpers ----------------------------------------
__device__ __forceinline__ float to_tf32(float x) {
    float r;
    asm("cvt.rna.tf32.f32 %0, %1;" : "=f"(r) : "f"(x));
    return r;
}
__device__ __forceinline__ void split2(float x, float& h, float& l) {
    h = to_tf32(x);
    l = to_tf32(x - h);
}

// ---------------- rmsnorm ----------------------------------------------------
__global__ void rmsnorm_kernel(const float* __restrict__ X,
                               const float* __restrict__ sc,
                               float* __restrict__ O)
{
    long row = blockIdx.x;
    const float* x = X + row * DD;
    float* o = O + row * DD;
    int tid = threadIdx.x;
    float ss = 0.f;
    for (int i = tid; i < DD; i += 256) { float v = x[i]; ss += v * v; }
    __shared__ float red[256];
    red[tid] = ss; __syncthreads();
    for (int st = 128; st > 0; st >>= 1) {
        if (tid < st) red[tid] += red[tid + st];
        __syncthreads();
    }
    float inv = rsqrtf(red[0] / (float)DD + 1e-6f);
    for (int i = tid; i < DD; i += 256) o[i] = x[i] * inv * sc[i];
}

// ---------------- lora A projection: low[M,32] = X[M,K] @ a[K,32] -----------
__global__ void lora_a_kernel(const float* __restrict__ X, long sXb,
                              const float* __restrict__ Aw, long sAb,
                              float* __restrict__ low, long sLb, int K)
{
    int b = blockIdx.y;
    X += (long)b * sXb; Aw += (long)b * sAb; low += (long)b * sLb;
    int wid = threadIdx.x >> 5, lane = threadIdx.x & 31;
    int r = blockIdx.x * 8 + wid;
    const float* xr = X + (long)r * K;
    float acc = 0.f;
    #pragma unroll 8
    for (int k = 0; k < K; k++) acc += xr[k] * Aw[k * 32 + lane];
    low[r * 32 + lane] = acc;
}

// ---------------- generic 3xTF32 GEMM ---------------------------------------
// C = alpha*(A@B + LA@LB) + Res
// tiles: BM=128, BN=64, BK=32. 8 warps, warp tile 32x32.
// M % 128 == 0, N % 64 == 0, K % 32 == 0 (guaranteed by all call sites).
#define BM 128
#define BN 64
#define BK 32
#define LDA_S 36
#define LDB_S 68
#define SM_AH 0
#define SM_AL 4608
#define SM_BH 9216
#define SM_BL 11392
#define GEMM_SMEM_FLOATS 13568

typedef wmma::fragment<wmma::matrix_a, 16, 16, 8, wmma::precision::tf32, wmma::row_major> AFrag;
typedef wmma::fragment<wmma::matrix_b, 16, 16, 8, wmma::precision::tf32, wmma::row_major> BFrag;
typedef wmma::fragment<wmma::matrix_b, 16, 16, 8, wmma::precision::tf32, wmma::col_major> BFragC;
typedef wmma::fragment<wmma::accumulator, 16, 16, 8, float> CFrag;

__global__ void gemm3x_kernel(const float* __restrict__ A, int lda, long sAb,
                              const float* __restrict__ B, int ldb,
                              long sBhi, int zdivB, long sBlo,
                              const float* __restrict__ LA, long sLAb,
                              const float* __restrict__ LB, long sLBb,
                              const float* __restrict__ Res, long sRb,
                              float* __restrict__ C, int ldc,
                              long sChi, int zdivC, long sClo,
                              int M, int N, int K, float alpha)
{
    extern __shared__ float sm[];
    float* sAh = sm + SM_AH;
    float* sAl = sm + SM_AL;
    float* sBh = sm + SM_BH;
    float* sBl = sm + SM_BL;

    int z = blockIdx.z;
    A += (long)z * sAb;
    B += (long)(z / zdivB) * sBhi + (long)(z % zdivB) * sBlo;
    if (LA) { LA += (long)z * sLAb; LB += (long)z * sLBb; }
    if (Res) Res += (long)z * sRb;
    C += (long)(z / zdivC) * sChi + (long)(z % zdivC) * sClo;

    int tid = threadIdx.x;
    int rowBase = blockIdx.y * BM;
    int colBase = blockIdx.x * BN;
    int wid = tid >> 5;
    int wm = wid & 3, wn = wid >> 2;

    CFrag c[2][2];
    #pragma unroll
    for (int i = 0; i < 2; i++)
        #pragma unroll
        for (int j = 0; j < 2; j++)
            wmma::fill_fragment(c[i][j], 0.f);

    int ar = tid >> 3;           // 0..31
    int ak = (tid & 7) << 2;     // 0..28
    int bk = tid >> 4;           // 0..15
    int bn = (tid & 15) << 2;    // 0..60

    for (int k0 = 0; k0 < K; k0 += BK) {
        #pragma unroll
        for (int p = 0; p < 4; p++) {
            int rr = ar + p * 32;
            float4 v = *(const float4*)(A + (long)(rowBase + rr) * lda + k0 + ak);
            float h, l;
            int off = rr * LDA_S + ak;
            split2(v.x, h, l); sAh[off + 0] = h; sAl[off + 0] = l;
            split2(v.y, h, l); sAh[off + 1] = h; sAl[off + 1] = l;
            split2(v.z, h, l); sAh[off + 2] = h; sAl[off + 2] = l;
            split2(v.w, h, l); sAh[off + 3] = h; sAl[off + 3] = l;
        }
        #pragma unroll
        for (int p = 0; p < 2; p++) {
            int kk = bk + p * 16;
            float4 v = *(const float4*)(B + (long)(k0 + kk) * ldb + colBase + bn);
            float h, l;
            int off = kk * LDB_S + bn;
            split2(v.x, h, l); sBh[off + 0] = h; sBl[off + 0] = l;
            split2(v.y, h, l); sBh[off + 1] = h; sBl[off + 1] = l;
            split2(v.z, h, l); sBh[off + 2] = h; sBl[off + 2] = l;
            split2(v.w, h, l); sBh[off + 3] = h; sBl[off + 3] = l;
        }
        __syncthreads();
        #pragma unroll
        for (int ks = 0; ks < 4; ks++) {
            AFrag ah[2], al[2];
            BFrag bh[2], bl[2];
            #pragma unroll
            for (int mt = 0; mt < 2; mt++) {
                wmma::load_matrix_sync(ah[mt], &sAh[(wm * 32 + mt * 16) * LDA_S + ks * 8], LDA_S);
                wmma::load_matrix_sync(al[mt], &sAl[(wm * 32 + mt * 16) * LDA_S + ks * 8], LDA_S);
            }
            #pragma unroll
            for (int nt = 0; nt < 2; nt++) {
                wmma::load_matrix_sync(bh[nt], &sBh[(ks * 8) * LDB_S + wn * 32 + nt * 16], LDB_S);
                wmma::load_matrix_sync(bl[nt], &sBl[(ks * 8) * LDB_S + wn * 32 + nt * 16], LDB_S);
            }
            #pragma unroll
            for (int mt = 0; mt < 2; mt++)
                #pragma unroll
                for (int nt = 0; nt < 2; nt++) {
                    wmma::mma_sync(c[mt][nt], ah[mt], bh[nt], c[mt][nt]);
                    wmma::mma_sync(c[mt][nt], ah[mt], bl[nt], c[mt][nt]);
                    wmma::mma_sync(c[mt][nt], al[mt], bh[nt], c[mt][nt]);
                }
        }
        __syncthreads();
    }

    if (LA) {  // one extra 32-K stage: LA[M,32] @ LB[32,N] (LB ld = ldc)
        #pragma unroll
        for (int p = 0; p < 4; p++) {
            int rr = ar + p * 32;
            float4 v = *(const float4*)(LA + (long)(rowBase + rr) * RR + ak);
            float h, l;
            int off = rr * LDA_S + ak;
            split2(v.x, h, l); sAh[off + 0] = h; sAl[off + 0] = l;
            split2(v.y, h, l); sAh[off + 1] = h; sAl[off + 1] = l;
            split2(v.z, h, l); sAh[off + 2] = h; sAl[off + 2] = l;
            split2(v.w, h, l); sAh[off + 3] = h; sAl[off + 3] = l;
        }
        #pragma unroll
        for (int p = 0; p < 2; p++) {
            int kk = bk + p * 16;
            float4 v = *(const float4*)(LB + (long)kk * ldc + colBase + bn);
            float h, l;
            int off = kk * LDB_S + bn;
            split2(v.x, h, l); sBh[off + 0] = h; sBl[off + 0] = l;
            split2(v.y, h, l); sBh[off + 1] = h; sBl[off + 1] = l;
            split2(v.z, h, l); sBh[off + 2] = h; sBl[off + 2] = l;
            split2(v.w, h, l); sBh[off + 3] = h; sBl[off + 3] = l;
        }
        __syncthreads();
        #pragma unroll
        for (int ks = 0; ks < 4; ks++) {
            AFrag ah[2], al[2];
            BFrag bh[2], bl[2];
            #pragma unroll
            for (int mt = 0; mt < 2; mt++) {
                wmma::load_matrix_sync(ah[mt], &sAh[(wm * 32 + mt * 16) * LDA_S + ks * 8], LDA_S);
                wmma::load_matrix_sync(al[mt], &sAl[(wm * 32 + mt * 16) * LDA_S + ks * 8], LDA_S);
            }
            #pragma unroll
            for (int nt = 0; nt < 2; nt++) {
                wmma::load_matrix_sync(bh[nt], &sBh[(ks * 8) * LDB_S + wn * 32 + nt * 16], LDB_S);
                wmma::load_matrix_sync(bl[nt], &sBl[(ks * 8) * LDB_S + wn * 32 + nt * 16], LDB_S);
            }
            #pragma unroll
            for (int mt = 0; mt < 2; mt++)
                #pragma unroll
                for (int nt = 0; nt < 2; nt++) {
                    wmma::mma_sync(c[mt][nt], ah[mt], bh[nt], c[mt][nt]);
                    wmma::mma_sync(c[mt][nt], ah[mt], bl[nt], c[mt][nt]);
                    wmma::mma_sync(c[mt][nt], al[mt], bh[nt], c[mt][nt]);
                }
        }
        __syncthreads();
    }

    // epilogue: scale, stage to smem, add residual, store
    #pragma unroll
    for (int mt = 0; mt < 2; mt++)
        #pragma unroll
        for (int nt = 0; nt < 2; nt++) {
            #pragma unroll
            for (int i = 0; i < c[mt][nt].num_elements; i++)
                c[mt][nt].x[i] *= alpha;
            wmma::store_matrix_sync(&sm[(wm * 32 + mt * 16) * LDB_S + wn * 32 + nt * 16],
                                    c[mt][nt], LDB_S, wmma::mem_row_major);
        }
    __syncthreads();

    int cr = tid >> 4;           // 0..15
    int cn = (tid & 15) << 2;
    #pragma unroll
    for (int p = 0; p < 8; p++) {
        int r = cr + p * 16;
        float4 v = *(float4*)&sm[r * LDB_S + cn];
        if (Res) {
            float4 rv = *(const float4*)(Res + (long)(rowBase + r) * ldc + colBase + cn);
            v.x += rv.x; v.y += rv.y; v.z += rv.z; v.w += rv.w;
        }
        *(float4*)(C + (long)(rowBase + r) * ldc + colBase + cn) = v;
    }
}

// ---------------- 3xTF32 attention scores: S = Q @ K^T -----------------------
#define SC_SMEM_FLOATS 17408
__global__ void score3x_kernel(const float* __restrict__ Q,
                               const float* __restrict__ Km,
                               float* __restrict__ S, int Lq, int Lk)
{
    extern __shared__ float sm[];
    float* Qh = sm;
    float* Ql = sm + 4352;
    float* Kh = sm + 8704;
    float* Kl = sm + 13056;

    int z = blockIdx.z; int b = z / HH; int h = z % HH;
    const float* q = Q + (long)b * Lq * DD + h * HDD;
    const float* k = Km + (long)b * Lk * DD + h * HDD;
    float* s = S + (long)z * Lq * Lk;

    int tid = threadIdx.x;
    int qBase = blockIdx.y * 64, kBase = blockIdx.x * 64;

    int r = tid >> 4;            // 0..15
    int c4 = (tid & 15) << 2;    // 0..60
    #pragma unroll
    for (int p = 0; p < 4; p++) {
        int rr = r + p * 16;
        float4 v = *(const float4*)(q + (long)(qBase + rr) * DD + c4);
        float hh, ll;
        int off = rr * 68 + c4;
        split2(v.x, hh, ll); Qh[off + 0] = hh; Ql[off + 0] = ll;
        split2(v.y, hh, ll); Qh[off + 1] = hh; Ql[off + 1] = ll;
        split2(v.z, hh, ll); Qh[off + 2] = hh; Ql[off + 2] = ll;
        split2(v.w, hh, ll); Qh[off + 3] = hh; Ql[off + 3] = ll;
        float4 w = *(const float4*)(k + (long)(kBase + rr) * DD + c4);
        split2(w.x, hh, ll); Kh[off + 0] = hh; Kl[off + 0] = ll;
        split2(w.y, hh, ll); Kh[off + 1] = hh; Kl[off + 1] = ll;
        split2(w.z, hh, ll); Kh[off + 2] = hh; Kl[off + 2] = ll;
        split2(w.w, hh, ll); Kh[off + 3] = hh; Kl[off + 3] = ll;
    }
    __syncthreads();

    int wid = tid >> 5;
    int wm = wid & 1, wn = wid >> 1;   // 2 x 4 warps, warp tile 32x16

    CFrag c[2];
    wmma::fill_fragment(c[0], 0.f);
    wmma::fill_fragment(c[1], 0.f);

    #pragma unroll
    for (int ks = 0; ks < 8; ks++) {
        AFrag ah[2], al[2];
        BFragC bh, bl;
        #pragma unroll
        for (int mt = 0; mt < 2; mt++) {
            wmma::load_matrix_sync(ah[mt], &Qh[(wm * 32 + mt * 16) * 68 + ks * 8], 68);
            wmma::load_matrix_sync(al[mt], &Ql[(wm * 32 + mt * 16) * 68 + ks * 8], 68);
        }
        wmma::load_matrix_sync(bh, &Kh[(wn * 16) * 68 + ks * 8], 68);
        wmma::load_matrix_sync(bl, &Kl[(wn * 16) * 68 + ks * 8], 68);
        #pragma unroll
        for (int mt = 0; mt < 2; mt++) {
            wmma::mma_sync(c[mt], ah[mt], bh, c[mt]);
            wmma::mma_sync(c[mt], ah[mt], bl, c[mt]);
            wmma::mma_sync(c[mt], al[mt], bh, c[mt]);
        }
    }
    __syncthreads();
    #pragma unroll
    for (int mt = 0; mt < 2; mt++)
        wmma::store_matrix_sync(&sm[(wm * 32 + mt * 16) * 68 + wn * 16],
                                c[mt], 68, wmma::mem_row_major);
    __syncthreads();

    #pragma unroll
    for (int p = 0; p < 4; p++) {
        int rr = r + p * 16;
        *(float4*)(s + (long)(qBase + rr) * Lk + kBase + c4) = *(float4*)&sm[rr * 68 + c4];
    }
}

// ---------------- fused bias + softmax (warp per row, Lk=512) ---------------
__global__ void softmax_bias_kernel(float* __restrict__ S,
                                    const float* __restrict__ rel, int Lq)
{
    __shared__ float tbl[512];
    int z = blockIdx.y;
    int h = z % HH;
    int tid = threadIdx.x;
    if (rel) {
        for (int n = tid; n < 512; n += 256) {
            int bucket;
            if (n < 16) bucket = n;
            else {
                int lg = (int)(logf((float)n / 16.0f) / logf(8.0f) * 16.0f);
                bucket = 16 + lg; if (bucket > 31) bucket = 31;
            }
            tbl[n] = rel[bucket * HH + h];
        }
        __syncthreads();
    }
    int wid = tid >> 5, lane = tid & 31;
    int qrow = blockIdx.x * 8 + wid;
    float* s = S + ((long)z * Lq + qrow) * 512;

    float vals[16];
    float m = -INFINITY;
    #pragma unroll
    for (int j = 0; j < 16; j++) {
        int kk = lane + j * 32;
        float v = s[kk];
        if (rel) {
            int d = qrow - kk;
            v += (d >= 0) ? tbl[d] : (tbl[0] - 1e10f);
        }
        vals[j] = v;
        m = fmaxf(m, v);
    }
    #pragma unroll
    for (int o = 16; o; o >>= 1) m = fmaxf(m, __shfl_xor_sync(0xffffffffu, m, o));
    float sum = 0.f;
    #pragma unroll
    for (int j = 0; j < 16; j++) { vals[j] = expf(vals[j] - m); sum += vals[j]; }
    #pragma unroll
    for (int o = 16; o; o >>= 1) sum += __shfl_xor_sync(0xffffffffu, sum, o);
    float inv = 1.f / sum;
    #pragma unroll
    for (int j = 0; j < 16; j++) s[lane + j * 32] = vals[j] * inv;
}

// ---------------- gated gelu -------------------------------------------------
__global__ void gelu_mul_kernel(float* __restrict__ h0,
                                const float* __restrict__ h1, long n)
{
    long i = (long)blockIdx.x * blockDim.x + threadIdx.x;
    if (i < n) {
        float x = h0[i];
        float g = 0.5f * x * (1.0f + erff(x * 0.70710678118654752f));
        h0[i] = g * h1[i];
    }
}

// ---------------- host side --------------------------------------------------
static float* sym_addr(const void* sym)
{
    void* p = nullptr;
    cudaGetSymbolAddress(&p, sym);
    return (float*)p;
}

#define GEMM_SMEM_BYTES (GEMM_SMEM_FLOATS * 4)
#define SC_SMEM_BYTES   (SC_SMEM_FLOATS * 4)

static void launch_gemm3x(const float* A, int lda, long sAb,
                          const float* B, int ldb, long sBhi, int zdivB, long sBlo,
                          const float* LA, long sLAb,
                          const float* LB, long sLBb,
                          const float* Res, long sRb,
                          float* C, int ldc, long sChi, int zdivC, long sClo,
                          int M, int N, int K, float alpha, int Z)
{
    dim3 g(N / BN, M / BM, Z);
    gemm3x_kernel<<<g, 256, GEMM_SMEM_BYTES>>>(A, lda, sAb, B, ldb, sBhi, zdivB, sBlo,
                                               LA, sLAb, LB, sLBb, Res, sRb,
                                               C, ldc, sChi, zdivC, sClo, M, N, K, alpha);
}

extern "C" void kernel_launch(void* const* d_in, const int* in_sizes, int n_in,
                              void* d_out, int out_size)
{
    const float* inputs  = (const float*)d_in[0];
    const float* encoded = (const float*)d_in[1];
    const float* qa = (const float*)d_in[2];
    const float* qb = (const float*)d_in[3];
    const float* ka = (const float*)d_in[4];
    const float* kb = (const float*)d_in[5];
    const float* va = (const float*)d_in[6];
    const float* vb = (const float*)d_in[7];
    const float* oa = (const float*)d_in[8];
    const float* ob = (const float*)d_in[9];
    const float* rel = (const float*)d_in[10];
    const float* ln1 = (const float*)d_in[11];
    const float* ln2 = (const float*)d_in[12];
    const float* ln3 = (const float*)d_in[13];
    const float* sWq = (const float*)d_in[14];
    const float* sWk = (const float*)d_in[15];
    const float* sWv = (const float*)d_in[16];
    const float* sWo = (const float*)d_in[17];
    const float* cWq = (const float*)d_in[18];
    const float* cWk = (const float*)d_in[19];
    const float* cWv = (const float*)d_in[20];
    const float* cWo = (const float*)d_in[21];
    const float* wi0 = (const float*)d_in[22];
    const float* wi1 = (const float*)d_in[23];
    const float* wom = (const float*)d_in[24];
    float* out = (float*)d_out;

    cudaFuncSetAttribute(gemm3x_kernel, cudaFuncAttributeMaxDynamicSharedMemorySize, GEMM_SMEM_BYTES);
    cudaFuncSetAttribute(score3x_kernel, cudaFuncAttributeMaxDynamicSharedMemorySize, SC_SMEM_BYTES);

    float* xn  = sym_addr(g_xn);
    float* q   = sym_addr(g_q);
    float* k   = sym_addr(g_k);
    float* v   = sym_addr(g_v);
    float* sc  = sym_addr(g_sc);
    float* ctx = sym_addr(g_ctx);
    float* xres= sym_addr(g_x);
    float* yres= sym_addr(g_y);
    float* low = sym_addr(g_low);
    float* h0  = sym_addr(g_h0);
    float* h1  = sym_addr(g_h1);

    const long sBL = (long)LL * DD;
    const long sEN = (long)ENCL * DD;
    const long sLow = (long)LL * RR;
    const long sA2 = 2L * DD * RR;
    const long sB2 = 2L * RR * DD;
    const long sSc = (long)LL * LL;
    const long sMLP = (long)LL * MLPD;
    const float qscale = 0.125f;

    dim3 gLA(LL / 8, BB);

    // ===================== self-attention =====================
    rmsnorm_kernel<<<BB * LL, 256>>>(inputs, ln1, xn);

    lora_a_kernel<<<gLA, 256>>>(xn, sBL, qa, sA2, low, sLow, DD);
    launch_gemm3x(xn, DD, sBL, sWq, DD, 0, 1, 0, low, sLow, qb, sB2,
                  nullptr, 0, q, DD, sBL, 1, 0, LL, DD, DD, qscale, BB);
    lora_a_kernel<<<gLA, 256>>>(xn, sBL, ka, sA2, low, sLow, DD);
    launch_gemm3x(xn, DD, sBL, sWk, DD, 0, 1, 0, low, sLow, kb, sB2,
                  nullptr, 0, k, DD, sBL, 1, 0, LL, DD, DD, 1.f, BB);
    lora_a_kernel<<<gLA, 256>>>(xn, sBL, va, sA2, low, sLow, DD);
    launch_gemm3x(xn, DD, sBL, sWv, DD, 0, 1, 0, low, sLow, vb, sB2,
                  nullptr, 0, v, DD, sBL, 1, 0, LL, DD, DD, 1.f, BB);

    {
        dim3 g(LL / 64, LL / 64, BB * HH);
        score3x_kernel<<<g, 256, SC_SMEM_BYTES>>>(q, k, sc, LL, LL);
    }
    {
        dim3 g(LL / 8, BB * HH);
        softmax_bias_kernel<<<g, 256>>>(sc, rel, LL);
    }
    // ctx = P @ V   (M=512, N=64, K=512), per (b,h) batch of 64
    launch_gemm3x(sc, LL, sSc, v, DD, sBL, HH, HDD, nullptr, 0, nullptr, 0,
                  nullptr, 0, ctx, DD, sBL, HH, HDD, LL, HDD, LL, 1.f, BB * HH);

    lora_a_kernel<<<gLA, 256>>>(ctx, sBL, oa, sA2, low, sLow, DD);
    launch_gemm3x(ctx, DD, sBL, sWo, DD, 0, 1, 0, low, sLow, ob, sB2,
                  inputs, sBL, xres, DD, sBL, 1, 0, LL, DD, DD, 1.f, BB);

    // ===================== cross-attention =====================
    rmsnorm_kernel<<<BB * LL, 256>>>(xres, ln2, xn);

    lora_a_kernel<<<gLA, 256>>>(xn, sBL, qa + (long)DD * RR, sA2, low, sLow, DD);
    launch_gemm3x(xn, DD, sBL, cWq, DD, 0, 1, 0, low, sLow, qb + (long)RR * DD, sB2,
                  nullptr, 0, q, DD, sBL, 1, 0, LL, DD, DD, qscale, BB);
    lora_a_kernel<<<gLA, 256>>>(encoded, sEN, ka + (long)DD * RR, sA2, low, sLow, DD);
    launch_gemm3x(encoded, DD, sEN, cWk, DD, 0, 1, 0, low, sLow, kb + (long)RR * DD, sB2,
                  nullptr, 0, k, DD, sEN, 1, 0, ENCL, DD, DD, 1.f, BB);
    lora_a_kernel<<<gLA, 256>>>(encoded, sEN, va + (long)DD * RR, sA2, low, sLow, DD);
    launch_gemm3x(encoded, DD, sEN, cWv, DD, 0, 1, 0, low, sLow, vb + (long)RR * DD, sB2,
                  nullptr, 0, v, DD, sEN, 1, 0, ENCL, DD, DD, 1.f, BB);

    {
        dim3 g(ENCL / 64, LL / 64, BB * HH);
        score3x_kernel<<<g, 256, SC_SMEM_BYTES>>>(q, k, sc, LL, ENCL);
    }
    {
        dim3 g(LL / 8, BB * HH);
        softmax_bias_kernel<<<g, 256>>>(sc, nullptr, LL);
    }
    launch_gemm3x(sc, ENCL, sSc, v, DD, sEN, HH, HDD, nullptr, 0, nullptr, 0,
                  nullptr, 0, ctx, DD, sBL, HH, HDD, LL, HDD, ENCL, 1.f, BB * HH);

    lora_a_kernel<<<gLA, 256>>>(ctx, sBL, oa + (long)DD * RR, sA2, low, sLow, DD);
    launch_gemm3x(ctx, DD, sBL, cWo, DD, 0, 1, 0, low, sLow, ob + (long)RR * DD, sB2,
                  xres, sBL, yres, DD, sBL, 1, 0, LL, DD, DD, 1.f, BB);

    // ===================== MLP =====================
    rmsnorm_kernel<<<BB * LL, 256>>>(yres, ln3, xn);

    launch_gemm3x(xn, DD, sBL, wi0, MLPD, 0, 1, 0, nullptr, 0, nullptr, 0,
                  nullptr, 0, h0, MLPD, sMLP, 1, 0, LL, MLPD, DD, 1.f, BB);
    launch_gemm3x(xn, DD, sBL, wi1, MLPD, 0, 1, 0, nullptr, 0, nullptr, 0,
                  nullptr, 0, h1, MLPD, sMLP, 1, 0, LL, MLPD, DD, 1.f, BB);
    {
        long n = (long)BB * LL * MLPD;
        gelu_mul_kernel<<<(unsigned)((n + 255) / 256), 256>>>(h0, h1, n);
    }
    launch_gemm3x(h0, MLPD, sMLP, wom, DD, 0, 1, 0, nullptr, 0, nullptr, 0,
                  yres, sBL, out, DD, sBL, 1, 0, LL, DD, MLPD, 1.f, BB);

    (void)in_sizes; (void)n_in; (void)out_size;
}

// round 3
// speedup vs baseline: 1.3505x; 1.2678x over previous
#include <cuda_runtime.h>
#include <math.h>
#include <mma.h>

using namespace nvcuda;

#define BB 4
#define LL 512
#define ENCL 512
#define DD 1024
#define HH 16
#define HDD 64
#define MLPD 4096
#define RR 32

// ---------------- scratch (device globals) ----------------------------------
__device__ float g_xn [BB*LL*DD];
__device__ float g_q  [BB*LL*DD];
__device__ float g_k  [BB*LL*DD];
__device__ float g_v  [BB*LL*DD];
__device__ float g_sc [BB*HH*LL*LL];
__device__ float g_ctx[BB*LL*DD];
__device__ float g_x  [BB*LL*DD];
__device__ float g_y  [BB*LL*DD];
__device__ float g_low[BB*LL*RR];
__device__ float g_h0 [BB*LL*MLPD];
__device__ float g_h1 [BB*LL*MLPD];

// ---------------- tf32 split helpers ----------------------------------------
__device__ __forceinline__ float to_tf32(float x) {
    float r;
    asm("cvt.rna.tf32.f32 %0, %1;" : "=f"(r) : "f"(x));
    return r;
}
__device__ __forceinline__ void split2(float x, float& h, float& l) {
    h = to_tf32(x);
    l = to_tf32(x - h);
}

// ---------------- rmsnorm ----------------------------------------------------
__global__ void rmsnorm_kernel(const float* __restrict__ X,
                               const float* __restrict__ sc,
                               float* __restrict__ O)
{
    long row = blockIdx.x;
    const float* x = X + row * DD;
    float* o = O + row * DD;
    int tid = threadIdx.x;
    float ss = 0.f;
    for (int i = tid; i < DD; i += 256) { float v = x[i]; ss += v * v; }
    __shared__ float red[256];
    red[tid] = ss; __syncthreads();
    for (int st = 128; st > 0; st >>= 1) {
        if (tid < st) red[tid] += red[tid + st];
        __syncthreads();
    }
    float inv = rsqrtf(red[0] / (float)DD + 1e-6f);
    for (int i = tid; i < DD; i += 256) o[i] = x[i] * inv * sc[i];
}

// ---------------- lora A: low[M,32] = X[M,K] @ a[K,32] ----------------------
// 8 warps per block, one row per warp, Aw chunks staged through smem.
__global__ __launch_bounds__(256)
void lora_a_kernel(const float* __restrict__ X, long sXb,
                   const float* __restrict__ Aw, long sAb,
                   float* __restrict__ low, long sLb, int K)
{
    int b = blockIdx.y;
    X += (long)b * sXb; Aw += (long)b * sAb; low += (long)b * sLb;
    __shared__ float sA[32 * 32];
    int tid = threadIdx.x;
    int wid = tid >> 5, lane = tid & 31;
    int row = blockIdx.x * 8 + wid;
    const float* xr = X + (long)row * K;

    float a0 = 0.f, a1 = 0.f, a2 = 0.f, a3 = 0.f;
    for (int k0 = 0; k0 < K; k0 += 32) {
        ((float4*)sA)[tid] = ((const float4*)(Aw + (long)k0 * 32))[tid];
        __syncthreads();
        #pragma unroll
        for (int j = 0; j < 8; j++) {
            float4 xv = *(const float4*)(xr + k0 + j * 4);
            a0 += xv.x * sA[(j * 4 + 0) * 32 + lane];
            a1 += xv.y * sA[(j * 4 + 1) * 32 + lane];
            a2 += xv.z * sA[(j * 4 + 2) * 32 + lane];
            a3 += xv.w * sA[(j * 4 + 3) * 32 + lane];
        }
        __syncthreads();
    }
    low[row * 32 + lane] = (a0 + a1) + (a2 + a3);
}

// ---------------- generic 3xTF32 GEMM ---------------------------------------
// C = alpha*(A@B + LA@LB) + Res. BK=32. warp tile MT*16 x NT*16.
typedef wmma::fragment<wmma::matrix_a, 16, 16, 8, wmma::precision::tf32, wmma::row_major> AFrag;
typedef wmma::fragment<wmma::matrix_b, 16, 16, 8, wmma::precision::tf32, wmma::row_major> BFrag;
typedef wmma::fragment<wmma::matrix_b, 16, 16, 8, wmma::precision::tf32, wmma::col_major> BFragC;
typedef wmma::fragment<wmma::accumulator, 16, 16, 8, float> CFrag;

template<int BM, int BN, int MT, int NT, int WM, int WN>
__global__ __launch_bounds__(WM * WN * 32)
void gemm3x_kernel(const float* __restrict__ A, int lda, long sAb,
                   const float* __restrict__ B, int ldb,
                   long sBhi, int zdivB, long sBlo,
                   const float* __restrict__ LA, long sLAb,
                   const float* __restrict__ LB, long sLBb,
                   const float* __restrict__ Res, long sRb,
                   float* __restrict__ C, int ldc,
                   long sChi, int zdivC, long sClo,
                   int K, float alpha)
{
    constexpr int T   = WM * WN * 32;
    constexpr int LDA = 36;
    constexpr int LDB = BN + 4;
    constexpr int ASZ = BM * LDA;
    constexpr int BSZ = 32 * LDB;
    extern __shared__ float sm[];
    float* sAh = sm;
    float* sAl = sm + ASZ;
    float* sBh = sm + 2 * ASZ;
    float* sBl = sm + 2 * ASZ + BSZ;

    int z = blockIdx.z;
    A += (long)z * sAb;
    B += (long)(z / zdivB) * sBhi + (long)(z % zdivB) * sBlo;
    if (LA) { LA += (long)z * sLAb; LB += (long)z * sLBb; }
    if (Res) Res += (long)z * sRb;
    C += (long)(z / zdivC) * sChi + (long)(z % zdivC) * sClo;

    int tid = threadIdx.x;
    int wid = tid >> 5;
    int wm = wid % WM, wn = wid / WM;
    int rowBase = blockIdx.y * BM;
    int colBase = blockIdx.x * BN;

    CFrag c[MT][NT];
    #pragma unroll
    for (int i = 0; i < MT; i++)
        #pragma unroll
        for (int j = 0; j < NT; j++)
            wmma::fill_fragment(c[i][j], 0.f);

    // loader maps
    int ar = tid >> 3;                 // row within pass (A rows per pass = T/8)
    int ak = (tid & 7) << 2;
    constexpr int AROWS = T / 8;
    constexpr int APASS = BM / AROWS;
    constexpr int BF4R  = BN / 4;
    int bk = tid / BF4R;
    int bn = (tid % BF4R) << 2;
    constexpr int BROWS = T / BF4R;
    constexpr int BPASS = 32 / BROWS;

    auto stage = [&](const float* Ap, int ldA_, const float* Bp, int ldB_, int k0) {
        #pragma unroll
        for (int p = 0; p < APASS; p++) {
            int rr = ar + p * AROWS;
            float4 v = *(const float4*)(Ap + (long)(rowBase + rr) * ldA_ + k0 + ak);
            float h, l;
            int off = rr * LDA + ak;
            split2(v.x, h, l); sAh[off + 0] = h; sAl[off + 0] = l;
            split2(v.y, h, l); sAh[off + 1] = h; sAl[off + 1] = l;
            split2(v.z, h, l); sAh[off + 2] = h; sAl[off + 2] = l;
            split2(v.w, h, l); sAh[off + 3] = h; sAl[off + 3] = l;
        }
        #pragma unroll
        for (int p = 0; p < BPASS; p++) {
            int kk = bk + p * BROWS;
            float4 v = *(const float4*)(Bp + (long)(k0 + kk) * ldB_ + colBase + bn);
            float h, l;
            int off = kk * LDB + bn;
            split2(v.x, h, l); sBh[off + 0] = h; sBl[off + 0] = l;
            split2(v.y, h, l); sBh[off + 1] = h; sBl[off + 1] = l;
            split2(v.z, h, l); sBh[off + 2] = h; sBl[off + 2] = l;
            split2(v.w, h, l); sBh[off + 3] = h; sBl[off + 3] = l;
        }
    };

    auto compute = [&]() {
        #pragma unroll
        for (int ks = 0; ks < 4; ks++) {
            AFrag ah[MT], al[MT];
            #pragma unroll
            for (int mt = 0; mt < MT; mt++) {
                int r0 = (wm * MT + mt) * 16;
                wmma::load_matrix_sync(ah[mt], &sAh[r0 * LDA + ks * 8], LDA);
                wmma::load_matrix_sync(al[mt], &sAl[r0 * LDA + ks * 8], LDA);
            }
            #pragma unroll
            for (int nt = 0; nt < NT; nt++) {
                BFrag bh, bl;
                int c0 = (wn * NT + nt) * 16;
                wmma::load_matrix_sync(bh, &sBh[(ks * 8) * LDB + c0], LDB);
                wmma::load_matrix_sync(bl, &sBl[(ks * 8) * LDB + c0], LDB);
                #pragma unroll
                for (int mt = 0; mt < MT; mt++) {
                    wmma::mma_sync(c[mt][nt], ah[mt], bh, c[mt][nt]);
                    wmma::mma_sync(c[mt][nt], ah[mt], bl, c[mt][nt]);
                    wmma::mma_sync(c[mt][nt], al[mt], bh, c[mt][nt]);
                }
            }
        }
    };

    for (int k0 = 0; k0 < K; k0 += 32) {
        stage(A, lda, B, ldb, k0);
        __syncthreads();
        compute();
        __syncthreads();
    }
    if (LA) {
        stage(LA, RR, LB, ldc, 0);
        __syncthreads();
        compute();
        __syncthreads();
    }

    // epilogue: direct fragment store, residual via accumulator load
    #pragma unroll
    for (int mt = 0; mt < MT; mt++)
        #pragma unroll
        for (int nt = 0; nt < NT; nt++) {
            long r0 = rowBase + (wm * MT + mt) * 16;
            long c0 = colBase + (wn * NT + nt) * 16;
            if (Res) {
                CFrag rfrag;
                wmma::load_matrix_sync(rfrag, Res + r0 * ldc + c0, ldc, wmma::mem_row_major);
                #pragma unroll
                for (int i = 0; i < c[mt][nt].num_elements; i++)
                    c[mt][nt].x[i] = c[mt][nt].x[i] * alpha + rfrag.x[i];
            } else {
                #pragma unroll
                for (int i = 0; i < c[mt][nt].num_elements; i++)
                    c[mt][nt].x[i] *= alpha;
            }
            wmma::store_matrix_sync(C + r0 * ldc + c0, c[mt][nt], ldc, wmma::mem_row_major);
        }
}

#define SMEM_G128 ((2 * 128 * 36 + 2 * 32 * 132) * 4)
#define SMEM_G64  ((2 * 128 * 36 + 2 * 32 * 68) * 4)

// ---------------- 3xTF32 attention scores: S = Q @ K^T -----------------------
#define SC_SMEM_FLOATS 17408
__global__ void score3x_kernel(const float* __restrict__ Q,
                               const float* __restrict__ Km,
                               float* __restrict__ S, int Lq, int Lk)
{
    extern __shared__ float sm[];
    float* Qh = sm;
    float* Ql = sm + 4352;
    float* Kh = sm + 8704;
    float* Kl = sm + 13056;

    int z = blockIdx.z; int b = z / HH; int h = z % HH;
    const float* q = Q + (long)b * Lq * DD + h * HDD;
    const float* k = Km + (long)b * Lk * DD + h * HDD;
    float* s = S + (long)z * Lq * Lk;

    int tid = threadIdx.x;
    int qBase = blockIdx.y * 64, kBase = blockIdx.x * 64;

    int r = tid >> 4;
    int c4 = (tid & 15) << 2;
    #pragma unroll
    for (int p = 0; p < 4; p++) {
        int rr = r + p * 16;
        float4 v = *(const float4*)(q + (long)(qBase + rr) * DD + c4);
        float hh, ll;
        int off = rr * 68 + c4;
        split2(v.x, hh, ll); Qh[off + 0] = hh; Ql[off + 0] = ll;
        split2(v.y, hh, ll); Qh[off + 1] = hh; Ql[off + 1] = ll;
        split2(v.z, hh, ll); Qh[off + 2] = hh; Ql[off + 2] = ll;
        split2(v.w, hh, ll); Qh[off + 3] = hh; Ql[off + 3] = ll;
        float4 w = *(const float4*)(k + (long)(kBase + rr) * DD + c4);
        split2(w.x, hh, ll); Kh[off + 0] = hh; Kl[off + 0] = ll;
        split2(w.y, hh, ll); Kh[off + 1] = hh; Kl[off + 1] = ll;
        split2(w.z, hh, ll); Kh[off + 2] = hh; Kl[off + 2] = ll;
        split2(w.w, hh, ll); Kh[off + 3] = hh; Kl[off + 3] = ll;
    }
    __syncthreads();

    int wid = tid >> 5;
    int wm = wid & 1, wn = wid >> 1;

    CFrag c[2];
    wmma::fill_fragment(c[0], 0.f);
    wmma::fill_fragment(c[1], 0.f);

    #pragma unroll
    for (int ks = 0; ks < 8; ks++) {
        AFrag ah[2], al[2];
        BFragC bh, bl;
        #pragma unroll
        for (int mt = 0; mt < 2; mt++) {
            wmma::load_matrix_sync(ah[mt], &Qh[(wm * 32 + mt * 16) * 68 + ks * 8], 68);
            wmma::load_matrix_sync(al[mt], &Ql[(wm * 32 + mt * 16) * 68 + ks * 8], 68);
        }
        wmma::load_matrix_sync(bh, &Kh[(wn * 16) * 68 + ks * 8], 68);
        wmma::load_matrix_sync(bl, &Kl[(wn * 16) * 68 + ks * 8], 68);
        #pragma unroll
        for (int mt = 0; mt < 2; mt++) {
            wmma::mma_sync(c[mt], ah[mt], bh, c[mt]);
            wmma::mma_sync(c[mt], ah[mt], bl, c[mt]);
            wmma::mma_sync(c[mt], al[mt], bh, c[mt]);
        }
    }
    #pragma unroll
    for (int mt = 0; mt < 2; mt++)
        wmma::store_matrix_sync(s + (long)(qBase + wm * 32 + mt * 16) * Lk + kBase + wn * 16,
                                c[mt], Lk, wmma::mem_row_major);
}

// ---------------- fused bias + softmax (warp per row, Lk=512) ---------------
__global__ void softmax_bias_kernel(float* __restrict__ S,
                                    const float* __restrict__ rel, int Lq)
{
    __shared__ float tbl[512];
    int z = blockIdx.y;
    int h = z % HH;
    int tid = threadIdx.x;
    if (rel) {
        for (int n = tid; n < 512; n += 256) {
            int bucket;
            if (n < 16) bucket = n;
            else {
                int lg = (int)(logf((float)n / 16.0f) / logf(8.0f) * 16.0f);
                bucket = 16 + lg; if (bucket > 31) bucket = 31;
            }
            tbl[n] = rel[bucket * HH + h];
        }
        __syncthreads();
    }
    int wid = tid >> 5, lane = tid & 31;
    int qrow = blockIdx.x * 8 + wid;
    float* s = S + ((long)z * Lq + qrow) * 512;

    float vals[16];
    float m = -INFINITY;
    #pragma unroll
    for (int j = 0; j < 16; j++) {
        int kk = lane + j * 32;
        float v = s[kk];
        if (rel) {
            int d = qrow - kk;
            v += (d >= 0) ? tbl[d] : (tbl[0] - 1e10f);
        }
        vals[j] = v;
        m = fmaxf(m, v);
    }
    #pragma unroll
    for (int o = 16; o; o >>= 1) m = fmaxf(m, __shfl_xor_sync(0xffffffffu, m, o));
    float sum = 0.f;
    #pragma unroll
    for (int j = 0; j < 16; j++) { vals[j] = expf(vals[j] - m); sum += vals[j]; }
    #pragma unroll
    for (int o = 16; o; o >>= 1) sum += __shfl_xor_sync(0xffffffffu, sum, o);
    float inv = 1.f / sum;
    #pragma unroll
    for (int j = 0; j < 16; j++) s[lane + j * 32] = vals[j] * inv;
}

// ---------------- gated gelu -------------------------------------------------
__global__ void gelu_mul_kernel(float* __restrict__ h0,
                                const float* __restrict__ h1, long n)
{
    long i = (long)blockIdx.x * blockDim.x + threadIdx.x;
    if (i < n) {
        float x = h0[i];
        float g = 0.5f * x * (1.0f + erff(x * 0.70710678118654752f));
        h0[i] = g * h1[i];
    }
}

// ---------------- host side --------------------------------------------------
static float* sym_addr(const void* sym)
{
    void* p = nullptr;
    cudaGetSymbolAddress(&p, sym);
    return (float*)p;
}

#define SC_SMEM_BYTES (SC_SMEM_FLOATS * 4)

static void launch_g128(const float* A, int lda, long sAb,
                        const float* B, int ldb, long sBhi, int zdivB, long sBlo,
                        const float* LA, long sLAb, const float* LB, long sLBb,
                        const float* Res, long sRb,
                        float* C, int ldc, long sChi, int zdivC, long sClo,
                        int M, int N, int K, float alpha, int Z)
{
    dim3 g(N / 128, M / 128, Z);
    gemm3x_kernel<128,128,4,4,2,2><<<g, 128, SMEM_G128>>>(A, lda, sAb, B, ldb, sBhi, zdivB, sBlo,
        LA, sLAb, LB, sLBb, Res, sRb, C, ldc, sChi, zdivC, sClo, K, alpha);
}

static void launch_g64(const float* A, int lda, long sAb,
                       const float* B, int ldb, long sBhi, int zdivB, long sBlo,
                       const float* Res, long sRb,
                       float* C, int ldc, long sChi, int zdivC, long sClo,
                       int M, int N, int K, float alpha, int Z)
{
    dim3 g(N / 64, M / 128, Z);
    gemm3x_kernel<128,64,4,2,2,2><<<g, 128, SMEM_G64>>>(A, lda, sAb, B, ldb, sBhi, zdivB, sBlo,
        nullptr, 0, nullptr, 0, Res, sRb, C, ldc, sChi, zdivC, sClo, K, alpha);
}

extern "C" void kernel_launch(void* const* d_in, const int* in_sizes, int n_in,
                              void* d_out, int out_size)
{
    const float* inputs  = (const float*)d_in[0];
    const float* encoded = (const float*)d_in[1];
    const float* qa = (const float*)d_in[2];
    const float* qb = (const float*)d_in[3];
    const float* ka = (const float*)d_in[4];
    const float* kb = (const float*)d_in[5];
    const float* va = (const float*)d_in[6];
    const float* vb = (const float*)d_in[7];
    const float* oa = (const float*)d_in[8];
    const float* ob = (const float*)d_in[9];
    const float* rel = (const float*)d_in[10];
    const float* ln1 = (const float*)d_in[11];
    const float* ln2 = (const float*)d_in[12];
    const float* ln3 = (const float*)d_in[13];
    const float* sWq = (const float*)d_in[14];
    const float* sWk = (const float*)d_in[15];
    const float* sWv = (const float*)d_in[16];
    const float* sWo = (const float*)d_in[17];
    const float* cWq = (const float*)d_in[18];
    const float* cWk = (const float*)d_in[19];
    const float* cWv = (const float*)d_in[20];
    const float* cWo = (const float*)d_in[21];
    const float* wi0 = (const float*)d_in[22];
    const float* wi1 = (const float*)d_in[23];
    const float* wom = (const float*)d_in[24];
    float* out = (float*)d_out;

    cudaFuncSetAttribute((const void*)gemm3x_kernel<128,128,4,4,2,2>,
                         cudaFuncAttributeMaxDynamicSharedMemorySize, SMEM_G128);
    cudaFuncSetAttribute((const void*)gemm3x_kernel<128,64,4,2,2,2>,
                         cudaFuncAttributeMaxDynamicSharedMemorySize, SMEM_G64);
    cudaFuncSetAttribute((const void*)score3x_kernel,
                         cudaFuncAttributeMaxDynamicSharedMemorySize, SC_SMEM_BYTES);

    float* xn  = sym_addr(g_xn);
    float* q   = sym_addr(g_q);
    float* k   = sym_addr(g_k);
    float* v   = sym_addr(g_v);
    float* sc  = sym_addr(g_sc);
    float* ctx = sym_addr(g_ctx);
    float* xres= sym_addr(g_x);
    float* yres= sym_addr(g_y);
    float* low = sym_addr(g_low);
    float* h0  = sym_addr(g_h0);
    float* h1  = sym_addr(g_h1);

    const long sBL = (long)LL * DD;
    const long sEN = (long)ENCL * DD;
    const long sLow = (long)LL * RR;
    const long sA2 = 2L * DD * RR;
    const long sB2 = 2L * RR * DD;
    const long sSc = (long)LL * LL;
    const long sMLP = (long)LL * MLPD;
    const float qscale = 0.125f;

    dim3 gLA(LL / 8, BB);

    // ===================== self-attention =====================
    rmsnorm_kernel<<<BB * LL, 256>>>(inputs, ln1, xn);

    lora_a_kernel<<<gLA, 256>>>(xn, sBL, qa, sA2, low, sLow, DD);
    launch_g128(xn, DD, sBL, sWq, DD, 0, 1, 0, low, sLow, qb, sB2,
                nullptr, 0, q, DD, sBL, 1, 0, LL, DD, DD, qscale, BB);
    lora_a_kernel<<<gLA, 256>>>(xn, sBL, ka, sA2, low, sLow, DD);
    launch_g128(xn, DD, sBL, sWk, DD, 0, 1, 0, low, sLow, kb, sB2,
                nullptr, 0, k, DD, sBL, 1, 0, LL, DD, DD, 1.f, BB);
    lora_a_kernel<<<gLA, 256>>>(xn, sBL, va, sA2, low, sLow, DD);
    launch_g128(xn, DD, sBL, sWv, DD, 0, 1, 0, low, sLow, vb, sB2,
                nullptr, 0, v, DD, sBL, 1, 0, LL, DD, DD, 1.f, BB);

    {
        dim3 g(LL / 64, LL / 64, BB * HH);
        score3x_kernel<<<g, 256, SC_SMEM_BYTES>>>(q, k, sc, LL, LL);
    }
    {
        dim3 g(LL / 8, BB * HH);
        softmax_bias_kernel<<<g, 256>>>(sc, rel, LL);
    }
    launch_g64(sc, LL, sSc, v, DD, sBL, HH, HDD, nullptr, 0,
               ctx, DD, sBL, HH, HDD, LL, HDD, LL, 1.f, BB * HH);

    lora_a_kernel<<<gLA, 256>>>(ctx, sBL, oa, sA2, low, sLow, DD);
    launch_g128(ctx, DD, sBL, sWo, DD, 0, 1, 0, low, sLow, ob, sB2,
                inputs, sBL, xres, DD, sBL, 1, 0, LL, DD, DD, 1.f, BB);

    // ===================== cross-attention =====================
    rmsnorm_kernel<<<BB * LL, 256>>>(xres, ln2, xn);

    lora_a_kernel<<<gLA, 256>>>(xn, sBL, qa + (long)DD * RR, sA2, low, sLow, DD);
    launch_g128(xn, DD, sBL, cWq, DD, 0, 1, 0, low, sLow, qb + (long)RR * DD, sB2,
                nullptr, 0, q, DD, sBL, 1, 0, LL, DD, DD, qscale, BB);
    lora_a_kernel<<<gLA, 256>>>(encoded, sEN, ka + (long)DD * RR, sA2, low, sLow, DD);
    launch_g128(encoded, DD, sEN, cWk, DD, 0, 1, 0, low, sLow, kb + (long)RR * DD, sB2,
                nullptr, 0, k, DD, sEN, 1, 0, ENCL, DD, DD, 1.f, BB);
    lora_a_kernel<<<gLA, 256>>>(encoded, sEN, va + (long)DD * RR, sA2, low, sLow, DD);
    launch_g128(encoded, DD, sEN, cWv, DD, 0, 1, 0, low, sLow, vb + (long)RR * DD, sB2,
                nullptr, 0, v, DD, sEN, 1, 0, ENCL, DD, DD, 1.f, BB);

    {
        dim3 g(ENCL / 64, LL / 64, BB * HH);
        score3x_kernel<<<g, 256, SC_SMEM_BYTES>>>(q, k, sc, LL, ENCL);
    }
    {
        dim3 g(LL / 8, BB * HH);
        softmax_bias_kernel<<<g, 256>>>(sc, nullptr, LL);
    }
    launch_g64(sc, ENCL, sSc, v, DD, sEN, HH, HDD, nullptr, 0,
               ctx, DD, sBL, HH, HDD, LL, HDD, ENCL, 1.f, BB * HH);

    lora_a_kernel<<<gLA, 256>>>(ctx, sBL, oa + (long)DD * RR, sA2, low, sLow, DD);
    launch_g128(ctx, DD, sBL, cWo, DD, 0, 1, 0, low, sLow, ob + (long)RR * DD, sB2,
                xres, sBL, yres, DD, sBL, 1, 0, LL, DD, DD, 1.f, BB);

    // ===================== MLP =====================
    rmsnorm_kernel<<<BB * LL, 256>>>(yres, ln3, xn);

    launch_g128(xn, DD, sBL, wi0, MLPD, 0, 1, 0, nullptr, 0, nullptr, 0,
                nullptr, 0, h0, MLPD, sMLP, 1, 0, LL, MLPD, DD, 1.f, BB);
    launch_g128(xn, DD, sBL, wi1, MLPD, 0, 1, 0, nullptr, 0, nullptr, 0,
                nullptr, 0, h1, MLPD, sMLP, 1, 0, LL, MLPD, DD, 1.f, BB);
    {
        long n = (long)BB * LL * MLPD;
        gelu_mul_kernel<<<(unsigned)((n + 255) / 256), 256>>>(h0, h1, n);
    }
    launch_g128(h0, MLPD, sMLP, wom, DD, 0, 1, 0, nullptr, 0, nullptr, 0,
                yres, sBL, out, DD, sBL, 1, 0, LL, DD, MLPD, 1.f, BB);

    (void)in_sizes; (void)n_in; (void)out_size;
}

// round 8
// speedup vs baseline: 1.3631x; 1.0093x over previous
#include <cuda_runtime.h>
#include <math.h>
#include <mma.h>

using namespace nvcuda;

#define BB 4
#define LL 512
#define ENCL 512
#define DD 1024
#define HH 16
#define HDD 64
#define MLPD 4096
#define RR 32

// ---------------- scratch (device globals) ----------------------------------
__device__ float g_xn  [BB*LL*DD];
__device__ float g_qkv [3*BB*LL*DD];
__device__ float g_w   [3*BB*DD*DD];
__device__ float g_sc  [BB*HH*LL*LL];
__device__ float g_ctx [BB*LL*DD];
__device__ float g_x   [BB*LL*DD];
__device__ float g_y   [BB*LL*DD];
__device__ float g_h0  [BB*LL*MLPD];
__device__ float g_h1  [BB*LL*MLPD];

// ---------------- tf32 split helpers ----------------------------------------
__device__ __forceinline__ float to_tf32(float x) {
    float r;
    asm("cvt.rna.tf32.f32 %0, %1;" : "=f"(r) : "f"(x));
    return r;
}
__device__ __forceinline__ void split2(float x, float& h, float& l) {
    h = to_tf32(x);
    l = to_tf32(x - h);
}

// ---------------- rmsnorm ----------------------------------------------------
__global__ void rmsnorm_kernel(const float* __restrict__ X,
                               const float* __restrict__ sc,
                               float* __restrict__ O)
{
    long row = blockIdx.x;
    const float* x = X + row * DD;
    float* o = O + row * DD;
    int tid = threadIdx.x;
    float ss = 0.f;
    for (int i = tid; i < DD; i += 256) { float v = x[i]; ss += v * v; }
    __shared__ float red[256];
    red[tid] = ss; __syncthreads();
    for (int st = 128; st > 0; st >>= 1) {
        if (tid < st) red[tid] += red[tid + st];
        __syncthreads();
    }
    float inv = rsqrtf(red[0] / (float)DD + 1e-6f);
    for (int i = tid; i < DD; i += 256) o[i] = x[i] * inv * sc[i];
}

// ---------------- pipelined 3xTF32 GEMM --------------------------------------
// C = alpha*(A@B) + Res. Generalized per-z offsets: off = (z/div)*hi + (z%div)*lo.
typedef wmma::fragment<wmma::matrix_a, 16, 16, 8, wmma::precision::tf32, wmma::row_major> AFrag;
typedef wmma::fragment<wmma::matrix_b, 16, 16, 8, wmma::precision::tf32, wmma::row_major> BFrag;
typedef wmma::fragment<wmma::matrix_b, 16, 16, 8, wmma::precision::tf32, wmma::col_major> BFragC;
typedef wmma::fragment<wmma::accumulator, 16, 16, 8, float> CFrag;

template<int BM, int BN, int MT, int NT, int WM, int WN>
__global__ __launch_bounds__(WM * WN * 32, 1)
void gemm_pipe(const float* __restrict__ A, int lda, long sAhi, int zdivA, long sAlo,
               const float* __restrict__ B, int ldb, long sBhi, int zdivB, long sBlo,
               const float* __restrict__ Res, long sRhi, int zdivR, long sRlo,
               float* __restrict__ C, int ldc, long sChi, int zdivC, long sClo,
               int K, float alpha)
{
    constexpr int T   = WM * WN * 32;
    constexpr int LDA = 36;
    constexpr int LDB = BN + 4;
    constexpr int ASZ = BM * LDA;
    constexpr int BSZ = 32 * LDB;
    constexpr int BUF = 2 * ASZ + 2 * BSZ;
    extern __shared__ float sm[];

    int z = blockIdx.z;
    A += (long)(z / zdivA) * sAhi + (long)(z % zdivA) * sAlo;
    B += (long)(z / zdivB) * sBhi + (long)(z % zdivB) * sBlo;
    if (Res) Res += (long)(z / zdivR) * sRhi + (long)(z % zdivR) * sRlo;
    C += (long)(z / zdivC) * sChi + (long)(z % zdivC) * sClo;

    int tid = threadIdx.x;
    int wid = tid >> 5;
    int wm = wid % WM, wn = wid / WM;
    int rowBase = blockIdx.y * BM;
    int colBase = blockIdx.x * BN;

    CFrag c[MT][NT];
    #pragma unroll
    for (int i = 0; i < MT; i++)
        #pragma unroll
        for (int j = 0; j < NT; j++)
            wmma::fill_fragment(c[i][j], 0.f);

    constexpr int AROWS = T / 8;        // 8 float4 per 32-float A row
    constexpr int APASS = BM / AROWS;
    constexpr int BF4R  = BN / 4;
    constexpr int BROWS = T / BF4R;
    constexpr int BPASS = 32 / BROWS;
    int ar = tid >> 3, ak = (tid & 7) << 2;
    int bk = tid / BF4R, bn = (tid % BF4R) << 2;

    float4 ra[APASS], rb[BPASS];

    auto fetch = [&](int k0) {
        #pragma unroll
        for (int p = 0; p < APASS; p++)
            ra[p] = *(const float4*)(A + (long)(rowBase + ar + p * AROWS) * lda + k0 + ak);
        #pragma unroll
        for (int p = 0; p < BPASS; p++)
            rb[p] = *(const float4*)(B + (long)(k0 + bk + p * BROWS) * ldb + colBase + bn);
    };

    auto store = [&](int buf) {
        float* sAh = sm + buf * BUF;
        float* sAl = sAh + ASZ;
        float* sBh = sAl + ASZ;
        float* sBl = sBh + BSZ;
        #pragma unroll
        for (int p = 0; p < APASS; p++) {
            int off = (ar + p * AROWS) * LDA + ak;
            float h, l;
            split2(ra[p].x, h, l); sAh[off + 0] = h; sAl[off + 0] = l;
            split2(ra[p].y, h, l); sAh[off + 1] = h; sAl[off + 1] = l;
            split2(ra[p].z, h, l); sAh[off + 2] = h; sAl[off + 2] = l;
            split2(ra[p].w, h, l); sAh[off + 3] = h; sAl[off + 3] = l;
        }
        #pragma unroll
        for (int p = 0; p < BPASS; p++) {
            int off = (bk + p * BROWS) * LDB + bn;
            float h, l;
            split2(rb[p].x, h, l); sBh[off + 0] = h; sBl[off + 0] = l;
            split2(rb[p].y, h, l); sBh[off + 1] = h; sBl[off + 1] = l;
            split2(rb[p].z, h, l); sBh[off + 2] = h; sBl[off + 2] = l;
            split2(rb[p].w, h, l); sBh[off + 3] = h; sBl[off + 3] = l;
        }
    };

    auto compute = [&](int buf) {
        float* sAh = sm + buf * BUF;
        float* sAl = sAh + ASZ;
        float* sBh = sAl + ASZ;
        float* sBl = sBh + BSZ;
        #pragma unroll
        for (int ks = 0; ks < 4; ks++) {
            AFrag ah[MT], al[MT];
            #pragma unroll
            for (int mt = 0; mt < MT; mt++) {
                int r0 = (wm * MT + mt) * 16;
                wmma::load_matrix_sync(ah[mt], &sAh[r0 * LDA + ks * 8], LDA);
                wmma::load_matrix_sync(al[mt], &sAl[r0 * LDA + ks * 8], LDA);
            }
            #pragma unroll
            for (int nt = 0; nt < NT; nt++) {
                BFrag bh, bl;
                int c0 = (wn * NT + nt) * 16;
                wmma::load_matrix_sync(bh, &sBh[(ks * 8) * LDB + c0], LDB);
                wmma::load_matrix_sync(bl, &sBl[(ks * 8) * LDB + c0], LDB);
                #pragma unroll
                for (int mt = 0; mt < MT; mt++) {
                    wmma::mma_sync(c[mt][nt], ah[mt], bh, c[mt][nt]);
                    wmma::mma_sync(c[mt][nt], ah[mt], bl, c[mt][nt]);
                    wmma::mma_sync(c[mt][nt], al[mt], bh, c[mt][nt]);
                }
            }
        }
    };

    int NI = K >> 5;
    fetch(0);
    store(0);
    for (int i = 0; i < NI; i++) {
        __syncthreads();
        if (i + 1 < NI) fetch((i + 1) << 5);
        compute(i & 1);
        if (i + 1 < NI) store((i + 1) & 1);
    }

    #pragma unroll
    for (int mt = 0; mt < MT; mt++)
        #pragma unroll
        for (int nt = 0; nt < NT; nt++) {
            long r0 = rowBase + (wm * MT + mt) * 16;
            long c0 = colBase + (wn * NT + nt) * 16;
            if (Res) {
                CFrag rfrag;
                wmma::load_matrix_sync(rfrag, Res + r0 * ldc + c0, ldc, wmma::mem_row_major);
                #pragma unroll
                for (int i = 0; i < c[mt][nt].num_elements; i++)
                    c[mt][nt].x[i] = c[mt][nt].x[i] * alpha + rfrag.x[i];
            } else {
                #pragma unroll
                for (int i = 0; i < c[mt][nt].num_elements; i++)
                    c[mt][nt].x[i] *= alpha;
            }
            wmma::store_matrix_sync(C + r0 * ldc + c0, c[mt][nt], ldc, wmma::mem_row_major);
        }
}

#define SMEM_P128 (2 * (2 * 128 * 36 + 2 * 32 * 132) * 4)
#define SMEM_P64  (2 * (2 * 128 * 36 + 2 * 32 * 68) * 4)

// ---------------- 3xTF32 attention scores: S = alpha * Q @ K^T ---------------
#define SC_SMEM_FLOATS 17408
__global__ void score3x_kernel(const float* __restrict__ Q,
                               const float* __restrict__ Km,
                               float* __restrict__ S, int Lq, int Lk, float alpha)
{
    extern __shared__ float sm[];
    float* Qh = sm;
    float* Ql = sm + 4352;
    float* Kh = sm + 8704;
    float* Kl = sm + 13056;

    int z = blockIdx.z; int b = z / HH; int h = z % HH;
    const float* q = Q + (long)b * Lq * DD + h * HDD;
    const float* k = Km + (long)b * Lk * DD + h * HDD;
    float* s = S + (long)z * Lq * Lk;

    int tid = threadIdx.x;
    int qBase = blockIdx.y * 64, kBase = blockIdx.x * 64;

    int r = tid >> 4;
    int c4 = (tid & 15) << 2;
    #pragma unroll
    for (int p = 0; p < 4; p++) {
        int rr = r + p * 16;
        float4 v = *(const float4*)(q + (long)(qBase + rr) * DD + c4);
        float hh, ll;
        int off = rr * 68 + c4;
        split2(v.x, hh, ll); Qh[off + 0] = hh; Ql[off + 0] = ll;
        split2(v.y, hh, ll); Qh[off + 1] = hh; Ql[off + 1] = ll;
        split2(v.z, hh, ll); Qh[off + 2] = hh; Ql[off + 2] = ll;
        split2(v.w, hh, ll); Qh[off + 3] = hh; Ql[off + 3] = ll;
        float4 w = *(const float4*)(k + (long)(kBase + rr) * DD + c4);
        split2(w.x, hh, ll); Kh[off + 0] = hh; Kl[off + 0] = ll;
        split2(w.y, hh, ll); Kh[off + 1] = hh; Kl[off + 1] = ll;
        split2(w.z, hh, ll); Kh[off + 2] = hh; Kl[off + 2] = ll;
        split2(w.w, hh, ll); Kh[off + 3] = hh; Kl[off + 3] = ll;
    }
    __syncthreads();

    int wid = tid >> 5;
    int wm = wid & 1, wn = wid >> 1;

    CFrag c[2];
    wmma::fill_fragment(c[0], 0.f);
    wmma::fill_fragment(c[1], 0.f);

    #pragma unroll
    for (int ks = 0; ks < 8; ks++) {
        AFrag ah[2], al[2];
        BFragC bh, bl;
        #pragma unroll
        for (int mt = 0; mt < 2; mt++) {
            wmma::load_matrix_sync(ah[mt], &Qh[(wm * 32 + mt * 16) * 68 + ks * 8], 68);
            wmma::load_matrix_sync(al[mt], &Ql[(wm * 32 + mt * 16) * 68 + ks * 8], 68);
        }
        wmma::load_matrix_sync(bh, &Kh[(wn * 16) * 68 + ks * 8], 68);
        wmma::load_matrix_sync(bl, &Kl[(wn * 16) * 68 + ks * 8], 68);
        #pragma unroll
        for (int mt = 0; mt < 2; mt++) {
            wmma::mma_sync(c[mt], ah[mt], bh, c[mt]);
            wmma::mma_sync(c[mt], ah[mt], bl, c[mt]);
            wmma::mma_sync(c[mt], al[mt], bh, c[mt]);
        }
    }
    #pragma unroll
    for (int mt = 0; mt < 2; mt++) {
        #pragma unroll
        for (int i = 0; i < c[mt].num_elements; i++) c[mt].x[i] *= alpha;
        wmma::store_matrix_sync(s + (long)(qBase + wm * 32 + mt * 16) * Lk + kBase + wn * 16,
                                c[mt], Lk, wmma::mem_row_major);
    }
}

// ---------------- fused bias + softmax (warp per row, Lk=512) ---------------
__global__ void softmax_bias_kernel(float* __restrict__ S,
                                    const float* __restrict__ rel, int Lq)
{
    __shared__ float tbl[512];
    int z = blockIdx.y;
    int h = z % HH;
    int tid = threadIdx.x;
    if (rel) {
        for (int n = tid; n < 512; n += 256) {
            int bucket;
            if (n < 16) bucket = n;
            else {
                int lg = (int)(logf((float)n / 16.0f) / logf(8.0f) * 16.0f);
                bucket = 16 + lg; if (bucket > 31) bucket = 31;
            }
            tbl[n] = rel[bucket * HH + h];
        }
        __syncthreads();
    }
    int wid = tid >> 5, lane = tid & 31;
    int qrow = blockIdx.x * 8 + wid;
    float* s = S + ((long)z * Lq + qrow) * 512;

    float vals[16];
    float m = -INFINITY;
    #pragma unroll
    for (int j = 0; j < 16; j++) {
        int kk = lane + j * 32;
        float v = s[kk];
        if (rel) {
            int d = qrow - kk;
            v += (d >= 0) ? tbl[d] : (tbl[0] - 1e10f);
        }
        vals[j] = v;
        m = fmaxf(m, v);
    }
    #pragma unroll
    for (int o = 16; o; o >>= 1) m = fmaxf(m, __shfl_xor_sync(0xffffffffu, m, o));
    float sum = 0.f;
    #pragma unroll
    for (int j = 0; j < 16; j++) { vals[j] = expf(vals[j] - m); sum += vals[j]; }
    #pragma unroll
    for (int o = 16; o; o >>= 1) sum += __shfl_xor_sync(0xffffffffu, sum, o);
    float inv = 1.f / sum;
    #pragma unroll
    for (int j = 0; j < 16; j++) s[lane + j * 32] = vals[j] * inv;
}

// ---------------- gated gelu -------------------------------------------------
__global__ void gelu_mul_kernel(float* __restrict__ h0,
                                const float* __restrict__ h1, long n)
{
    long i = (long)blockIdx.x * blockDim.x + threadIdx.x;
    if (i < n) {
        float x = h0[i];
        float g = 0.5f * x * (1.0f + erff(x * 0.70710678118654752f));
        h0[i] = g * h1[i];
    }
}

// ---------------- host side --------------------------------------------------
static float* sym_addr(const void* sym)
{
    void* p = nullptr;
    cudaGetSymbolAddress(&p, sym);
    return (float*)p;
}

#define SC_SMEM_BYTES (SC_SMEM_FLOATS * 4)

static void g128(const float* A, int lda, long sAhi, int zdivA, long sAlo,
                 const float* B, int ldb, long sBhi, int zdivB, long sBlo,
                 const float* Res, long sRhi, int zdivR, long sRlo,
                 float* C, int ldc, long sChi, int zdivC, long sClo,
                 int M, int N, int K, float alpha, int Z)
{
    dim3 g(N / 128, M / 128, Z);
    gemm_pipe<128,128,4,2,2,4><<<g, 256, SMEM_P128>>>(
        A, lda, sAhi, zdivA, sAlo, B, ldb, sBhi, zdivB, sBlo,
        Res, sRhi, zdivR, sRlo, C, ldc, sChi, zdivC, sClo, K, alpha);
}

static void g64(const float* A, int lda, long sAhi, int zdivA, long sAlo,
                const float* B, int ldb, long sBhi, int zdivB, long sBlo,
                float* C, int ldc, long sChi, int zdivC, long sClo,
                int M, int N, int K, float alpha, int Z)
{
    dim3 g(N / 64, M / 128, Z);
    gemm_pipe<128,64,4,2,2,2><<<g, 128, SMEM_P64>>>(
        A, lda, sAhi, zdivA, sAlo, B, ldb, sBhi, zdivB, sBlo,
        nullptr, 0, 1, 0, C, ldc, sChi, zdivC, sClo, K, alpha);
}

extern "C" void kernel_launch(void* const* d_in, const int* in_sizes, int n_in,
                              void* d_out, int out_size)
{
    const float* inputs  = (const float*)d_in[0];
    const float* encoded = (const float*)d_in[1];
    const float* qa = (const float*)d_in[2];
    const float* qb = (const float*)d_in[3];
    const float* ka = (const float*)d_in[4];
    const float* kb = (const float*)d_in[5];
    const float* va = (const float*)d_in[6];
    const float* vb = (const float*)d_in[7];
    const float* oa = (const float*)d_in[8];
    const float* ob = (const float*)d_in[9];
    const float* rel = (const float*)d_in[10];
    const float* ln1 = (const float*)d_in[11];
    const float* ln2 = (const float*)d_in[12];
    const float* ln3 = (const float*)d_in[13];
    const float* sWq = (const float*)d_in[14];
    const float* sWk = (const float*)d_in[15];
    const float* sWv = (const float*)d_in[16];
    const float* sWo = (const float*)d_in[17];
    const float* cWq = (const float*)d_in[18];
    const float* cWk = (const float*)d_in[19];
    const float* cWv = (const float*)d_in[20];
    const float* cWo = (const float*)d_in[21];
    const float* wi0 = (const float*)d_in[22];
    const float* wi1 = (const float*)d_in[23];
    const float* wom = (const float*)d_in[24];
    float* out = (float*)d_out;

    cudaFuncSetAttribute((const void*)gemm_pipe<128,128,4,2,2,4>,
                         cudaFuncAttributeMaxDynamicSharedMemorySize, SMEM_P128);
    cudaFuncSetAttribute((const void*)gemm_pipe<128,64,4,2,2,2>,
                         cudaFuncAttributeMaxDynamicSharedMemorySize, SMEM_P64);
    cudaFuncSetAttribute((const void*)score3x_kernel,
                         cudaFuncAttributeMaxDynamicSharedMemorySize, SC_SMEM_BYTES);

    float* xn  = sym_addr(g_xn);
    float* qkv = sym_addr(g_qkv);
    float* gw  = sym_addr(g_w);
    float* sc  = sym_addr(g_sc);
    float* ctx = sym_addr(g_ctx);
    float* xres= sym_addr(g_x);
    float* yres= sym_addr(g_y);
    float* h0  = sym_addr(g_h0);
    float* h1  = sym_addr(g_h1);

    const long sBL = (long)LL * DD;
    const long sEN = (long)ENCL * DD;
    const long sA2 = 2L * DD * RR;
    const long sB2 = 2L * RR * DD;
    const long sSc = (long)LL * LL;
    const long sMLP = (long)LL * MLPD;
    const long WSZ = (long)DD * DD;
    const long W4  = 4 * WSZ;
    const long Q4  = (long)BB * sBL;
    const long selB = (long)DD * RR;   // offset to cross-attn lora a slice
    const long selBb = (long)RR * DD;  // offset to cross-attn lora b slice
    const float qscale = 0.125f;

    // wprime: gw_out[b] = W + a[b] @ b[b]   (M=N=1024, K=32, Z=4)
    auto wprime = [&](const float* a, const float* bw, const float* W, float* outw) {
        g128(a, RR, sA2, 1, 0, bw, DD, sB2, 1, 0,
             W, 0, 1, 0, outw, DD, WSZ, 1, 0, DD, DD, RR, 1.f, BB);
    };

    // ===================== self-attention =====================
    rmsnorm_kernel<<<BB * LL, 256>>>(inputs, ln1, xn);
    wprime(qa, qb, sWq, gw + 0 * W4);
    wprime(ka, kb, sWk, gw + 1 * W4);
    wprime(va, vb, sWv, gw + 2 * W4);
    // merged QKV: Z=12, z = w*4 + b
    g128(xn, DD, 0, 4, sBL,
         gw, DD, W4, 4, WSZ,
         nullptr, 0, 1, 0,
         qkv, DD, Q4, 4, sBL,
         LL, DD, DD, 1.f, 12);
    {
        dim3 g(LL / 64, LL / 64, BB * HH);
        score3x_kernel<<<g, 256, SC_SMEM_BYTES>>>(qkv, qkv + Q4, sc, LL, LL, qscale);
    }
    {
        dim3 g(LL / 8, BB * HH);
        softmax_bias_kernel<<<g, 256>>>(sc, rel, LL);
    }
    g64(sc, LL, sSc, 1, 0,
        qkv + 2 * Q4, DD, sBL, 16, HDD,
        ctx, DD, sBL, 16, HDD,
        LL, HDD, LL, 1.f, BB * HH);
    wprime(oa, ob, sWo, gw);
    g128(ctx, DD, sBL, 1, 0, gw, DD, WSZ, 1, 0,
         inputs, sBL, 1, 0, xres, DD, sBL, 1, 0, LL, DD, DD, 1.f, BB);

    // ===================== cross-attention =====================
    rmsnorm_kernel<<<BB * LL, 256>>>(xres, ln2, xn);
    wprime(qa + selB, qb + selBb, cWq, gw + 0 * W4);
    wprime(ka + selB, kb + selBb, cWk, gw + 1 * W4);
    wprime(va + selB, vb + selBb, cWv, gw + 2 * W4);
    // q from xn
    g128(xn, DD, sBL, 1, 0, gw, DD, WSZ, 1, 0,
         nullptr, 0, 1, 0, qkv, DD, sBL, 1, 0, LL, DD, DD, 1.f, BB);
    // k,v from encoded: Z=8, z = w*4 + b
    g128(encoded, DD, 0, 4, sEN,
         gw + W4, DD, W4, 4, WSZ,
         nullptr, 0, 1, 0,
         qkv + Q4, DD, Q4, 4, sBL,
         ENCL, DD, DD, 1.f, 8);
    {
        dim3 g(ENCL / 64, LL / 64, BB * HH);
        score3x_kernel<<<g, 256, SC_SMEM_BYTES>>>(qkv, qkv + Q4, sc, LL, ENCL, qscale);
    }
    {
        dim3 g(LL / 8, BB * HH);
        softmax_bias_kernel<<<g, 256>>>(sc, nullptr, LL);
    }
    g64(sc, ENCL, sSc, 1, 0,
        qkv + 2 * Q4, DD, sEN, 16, HDD,
        ctx, DD, sBL, 16, HDD,
        LL, HDD, ENCL, 1.f, BB * HH);
    wprime(oa + selB, ob + selBb, cWo, gw);
    g128(ctx, DD, sBL, 1, 0, gw, DD, WSZ, 1, 0,
         xres, sBL, 1, 0, yres, DD, sBL, 1, 0, LL, DD, DD, 1.f, BB);

    // ===================== MLP =====================
    rmsnorm_kernel<<<BB * LL, 256>>>(yres, ln3, xn);
    g128(xn, DD, sBL, 1, 0, wi0, MLPD, 0, 1, 0,
         nullptr, 0, 1, 0, h0, MLPD, sMLP, 1, 0, LL, MLPD, DD, 1.f, BB);
    g128(xn, DD, sBL, 1, 0, wi1, MLPD, 0, 1, 0,
         nullptr, 0, 1, 0, h1, MLPD, sMLP, 1, 0, LL, MLPD, DD, 1.f, BB);
    {
        long n = (long)BB * LL * MLPD;
        gelu_mul_kernel<<<(unsigned)((n + 255) / 256), 256>>>(h0, h1, n);
    }
    g128(h0, MLPD, sMLP, 1, 0, wom, DD, 0, 1, 0,
         yres, sBL, 1, 0, out, DD, sBL, 1, 0, LL, DD, MLPD, 1.f, BB);

    (void)in_sizes; (void)n_in; (void)out_size;
}